// round 14
// baseline (speedup 1.0000x reference)
#include <cuda_runtime.h>
#include <cuda_fp16.h>
#include <math.h>

#define N_NODES 50000
#define N_EDGES 1600000
#define F_IN    256
#define F1T     200   // H1*F1
#define NH1     2
#define C_OUT   32
#define NEG_SLOPE 0.2f
#define FULLM   0xffffffffu

// ---------------- scratch (static device globals; no allocation) ----------------
__device__ int    g_cnt[N_NODES];
__device__ int    g_off[N_NODES + 1];
__device__ int    g_cur[N_NODES];
__device__ int    g_done;                        // last-block flag for histscan
__device__ int    g_psrc[N_EDGES];               // src node per edge, grouped by dst
__device__ float  g_z1f[(size_t)N_NODES * F1T];  // 40 MB (fp32 z1; L2-resident)
__device__ float  g_el1[N_NODES * NH1];
__device__ float  g_er1[N_NODES * NH1];
__device__ __half g_z2h[(size_t)N_NODES * C_OUT]; // 3.2 MB (fp16 z2)
__device__ float  g_el2[N_NODES];
__device__ float  g_er2[N_NODES];

// ---------------- helpers ----------------
__device__ __forceinline__ float warp_sum(float v) {
    #pragma unroll
    for (int o = 16; o; o >>= 1) v += __shfl_xor_sync(FULLM, v, o);
    return v;
}
__device__ __forceinline__ float lrelu(float x) { return x > 0.f ? x : NEG_SLOPE * x; }
__device__ __forceinline__ float elu1(float x)  { return x > 0.f ? x : (__expf(x) - 1.f); }
__device__ __forceinline__ unsigned tf32u(float x) {
    unsigned u;
    asm("cvt.rna.tf32.f32 %0, %1;" : "=r"(u) : "f"(x));
    return u;
}

__device__ __forceinline__ unsigned smem_u32(const void* p) {
    return (unsigned)__cvta_generic_to_shared(p);
}
__device__ __forceinline__ void cp_async16(void* dst_smem, const void* src_gmem) {
    asm volatile("cp.async.cg.shared.global [%0], [%1], 16;\n"
                 :: "r"(smem_u32(dst_smem)), "l"(src_gmem));
}
__device__ __forceinline__ void cp_commit() { asm volatile("cp.async.commit_group;\n"); }
template <int N>
__device__ __forceinline__ void cp_wait() { asm volatile("cp.async.wait_group %0;\n" :: "n"(N)); }

// ---------------- CSR build: fused hist + scan (last-block pattern) ----------------
#define HS_BLOCKS ((N_EDGES + 1023) / 1024)   // 1563
__global__ __launch_bounds__(1024) void k_histscan(const int* __restrict__ dst) {
    int tid = threadIdx.x;
    int e = blockIdx.x * 1024 + tid;
    if (e < N_EDGES) atomicAdd(&g_cnt[dst[e]], 1);

    __threadfence();
    __shared__ int s_last;
    __syncthreads();
    if (tid == 0) s_last = (atomicAdd(&g_done, 1) == gridDim.x - 1);
    __syncthreads();
    if (!s_last) return;

    const int CH = (N_NODES + 1023) / 1024;  // 49
    int beg = tid * CH;
    int end = min(beg + CH, N_NODES);
    int s = 0;
    for (int i = beg; i < end; i++) s += g_cnt[i];

    __shared__ int warp_sums[32];
    int lane = tid & 31, wid = tid >> 5;
    int v = s;
    #pragma unroll
    for (int o = 1; o < 32; o <<= 1) {
        int t = __shfl_up_sync(FULLM, v, o);
        if (lane >= o) v += t;
    }
    if (lane == 31) warp_sums[wid] = v;
    __syncthreads();
    if (wid == 0) {
        int w = warp_sums[lane];
        #pragma unroll
        for (int o = 1; o < 32; o <<= 1) {
            int t = __shfl_up_sync(FULLM, w, o);
            if (lane >= o) w += t;
        }
        warp_sums[lane] = w;
    }
    __syncthreads();
    int excl = (v - s) + (wid > 0 ? warp_sums[wid - 1] : 0);
    int run = excl;
    for (int i = beg; i < end; i++) {
        int c = g_cnt[i];
        g_off[i] = run;
        g_cur[i] = run;
        run += c;
    }
    if (tid == 1023) g_off[N_NODES] = run;
    if (tid == 0) g_done = 0;   // reset for next replay
}

__global__ void k_scatter(const int* __restrict__ src, const int* __restrict__ dst) {
    int e = blockIdx.x * blockDim.x + threadIdx.x;
    if (e < N_EDGES) {
        int p = atomicAdd(&g_cur[dst[e]], 1);
        g_psrc[p] = src[e];
    }
}

// ---------------- GEMM1 (tf32 mma) -> z1 fp32, + fused attention coefs ----------------
#define G1_BM 128
#define G1_BN 64
#define G1_BK 32
#define G1_LDA 36
#define G1_LDB 72
#define A_STAGE (G1_BM * G1_LDA)
#define B_STAGE (G1_BK * G1_LDB)
#define G1_SMEM ((2 * A_STAGE + 2 * B_STAGE) * 4)   // 55296 bytes dynamic
#define G1_NIT  (F_IN / G1_BK)

__device__ __forceinline__ void mma_tf32(float* d, const unsigned* a, const unsigned* b) {
    asm volatile(
        "mma.sync.aligned.m16n8k8.row.col.f32.tf32.tf32.f32 "
        "{%0,%1,%2,%3}, {%4,%5,%6,%7}, {%8,%9}, {%0,%1,%2,%3};"
        : "+f"(d[0]), "+f"(d[1]), "+f"(d[2]), "+f"(d[3])
        : "r"(a[0]), "r"(a[1]), "r"(a[2]), "r"(a[3]), "r"(b[0]), "r"(b[1]));
}

__global__ __launch_bounds__(256) void k_gemm1_tc(const float* __restrict__ A,
                                                  const float* __restrict__ B,
                                                  const float* __restrict__ al1,
                                                  const float* __restrict__ ar1) {
    extern __shared__ float smem[];
    float* sA = smem;                      // [2][128][36]
    float* sB = smem + 2 * A_STAGE;        // [2][32][72]
    __shared__ float s_al[F1T], s_ar[F1T];

    int tid = threadIdx.x;
    int lane = tid & 31, wid = tid >> 5;
    int wm = wid & 3, wn = wid >> 2;
    int bm = blockIdx.x * G1_BM, bn = blockIdx.y * G1_BN;
    int q = lane >> 2, r = lane & 3;

    for (int i = tid; i < F1T; i += 256) { s_al[i] = al1[i]; s_ar[i] = ar1[i]; }

    int am = tid >> 3;
    int akc = (tid & 7) * 4;

    auto load_stage = [&](int st, int k0) {
        float* a_s = sA + st * A_STAGE;
        float* b_s = sB + st * B_STAGE;
        #pragma unroll
        for (int it = 0; it < 4; it++) {
            int m = am + it * 32;
            float* dstp = &a_s[m * G1_LDA + akc];
            if (bm + m < N_NODES)
                cp_async16(dstp, &A[(size_t)(bm + m) * F_IN + k0 + akc]);
            else
                *(float4*)dstp = make_float4(0.f, 0.f, 0.f, 0.f);
        }
        #pragma unroll
        for (int it = 0; it < 2; it++) {
            int idx = tid + it * 256;
            int kk = idx >> 4;
            int nc = (idx & 15) * 4;
            float* dstp = &b_s[kk * G1_LDB + nc];
            if (bn + nc < F1T)
                cp_async16(dstp, &B[(size_t)(k0 + kk) * F1T + bn + nc]);
            else
                *(float4*)dstp = make_float4(0.f, 0.f, 0.f, 0.f);
        }
        cp_commit();
    };

    float acc[2][4][4] = {};

    load_stage(0, 0);

    #pragma unroll
    for (int it = 0; it < G1_NIT; it++) {
        if (it + 1 < G1_NIT) {
            load_stage((it + 1) & 1, (it + 1) * G1_BK);
            cp_wait<1>();
        } else {
            cp_wait<0>();
        }
        __syncthreads();

        const float* a_s = sA + (it & 1) * A_STAGE;
        const float* b_s = sB + (it & 1) * B_STAGE;

        #pragma unroll
        for (int k8 = 0; k8 < G1_BK / 8; k8++) {
            int kb = k8 * 8;
            unsigned af[2][4], bf[4][2];
            #pragma unroll
            for (int mt = 0; mt < 2; mt++) {
                int m0 = wm * 32 + mt * 16 + q;
                af[mt][0] = tf32u(a_s[m0 * G1_LDA + kb + r]);
                af[mt][1] = tf32u(a_s[(m0 + 8) * G1_LDA + kb + r]);
                af[mt][2] = tf32u(a_s[m0 * G1_LDA + kb + r + 4]);
                af[mt][3] = tf32u(a_s[(m0 + 8) * G1_LDA + kb + r + 4]);
            }
            #pragma unroll
            for (int nt = 0; nt < 4; nt++) {
                int n0 = wn * 32 + nt * 8 + q;
                bf[nt][0] = tf32u(b_s[(kb + r) * G1_LDB + n0]);
                bf[nt][1] = tf32u(b_s[(kb + r + 4) * G1_LDB + n0]);
            }
            #pragma unroll
            for (int mt = 0; mt < 2; mt++)
                #pragma unroll
                for (int nt = 0; nt < 4; nt++)
                    mma_tf32(acc[mt][nt], af[mt], bf[nt]);
        }
        __syncthreads();
    }

    // epilogue A: store z1 fp32
    #pragma unroll
    for (int mt = 0; mt < 2; mt++) {
        #pragma unroll
        for (int nt = 0; nt < 4; nt++) {
            int row = bm + wm * 32 + mt * 16 + q;
            int col = bn + wn * 32 + nt * 8 + 2 * r;
            if (col < F1T) {
                if (row < N_NODES) {
                    float* pp = &g_z1f[(size_t)row * F1T + col];
                    pp[0] = acc[mt][nt][0];
                    pp[1] = acc[mt][nt][1];
                }
                if (row + 8 < N_NODES) {
                    float* pp = &g_z1f[(size_t)(row + 8) * F1T + col];
                    pp[0] = acc[mt][nt][2];
                    pp[1] = acc[mt][nt][3];
                }
            }
        }
    }

    // epilogue B: partial el/er per row
    #pragma unroll
    for (int mt = 0; mt < 2; mt++) {
        float e0l = 0.f, e1l = 0.f, e0r = 0.f, e1r = 0.f;   // row r0
        float f0l = 0.f, f1l = 0.f, f0r = 0.f, f1r = 0.f;   // row r0+8
        #pragma unroll
        for (int nt = 0; nt < 4; nt++) {
            int colb = bn + wn * 32 + nt * 8 + 2 * r;
            #pragma unroll
            for (int cc = 0; cc < 2; cc++) {
                int c = colb + cc;
                if (c < F1T) {
                    float a = s_al[c], rr = s_ar[c];
                    float zt = acc[mt][nt][cc];
                    float zb = acc[mt][nt][2 + cc];
                    if (c < 100) { e0l += zt * a; e0r += zt * rr; f0l += zb * a; f0r += zb * rr; }
                    else         { e1l += zt * a; e1r += zt * rr; f1l += zb * a; f1r += zb * rr; }
                }
            }
        }
        #pragma unroll
        for (int o = 1; o <= 2; o <<= 1) {
            e0l += __shfl_xor_sync(FULLM, e0l, o); e1l += __shfl_xor_sync(FULLM, e1l, o);
            e0r += __shfl_xor_sync(FULLM, e0r, o); e1r += __shfl_xor_sync(FULLM, e1r, o);
            f0l += __shfl_xor_sync(FULLM, f0l, o); f1l += __shfl_xor_sync(FULLM, f1l, o);
            f0r += __shfl_xor_sync(FULLM, f0r, o); f1r += __shfl_xor_sync(FULLM, f1r, o);
        }
        if (r == 0) {
            int row = bm + wm * 32 + mt * 16 + q;
            if (row < N_NODES) {
                atomicAdd(&g_el1[2 * row],     e0l); atomicAdd(&g_el1[2 * row + 1], e1l);
                atomicAdd(&g_er1[2 * row],     e0r); atomicAdd(&g_er1[2 * row + 1], e1r);
            }
            if (row + 8 < N_NODES) {
                atomicAdd(&g_el1[2 * (row + 8)],     f0l); atomicAdd(&g_el1[2 * (row + 8) + 1], f1l);
                atomicAdd(&g_er1[2 * (row + 8)],     f0r); atomicAdd(&g_er1[2 * (row + 8) + 1], f1r);
            }
        }
    }
}

// ---------------- fused layer-1 aggregation + ELU + GEMM2 (paired) + attn2 coefs ----------------
// Gather layout: lane l (<25) covers features 8l..8l+7 via two LDG.128 per edge,
// no conversions. Head boundary f=100 inside lane 12 only:
// wlo = (l<=12)?w0:w1 (feats 8l..8l+3), whi = (l<=11)?w0:w1 (feats 8l+4..8l+7).
#define AG_BLOCKS (6 * 148)   // 888: one wave at 6 blocks/SM
#define WT_LD 216             // padded row (halfs): conflict-free int4 reads
__global__ __launch_bounds__(256, 6) void k_agg1_g2(const float* __restrict__ b1,
                                                    const float* __restrict__ W2,
                                                    const float* __restrict__ al2,
                                                    const float* __restrict__ ar2) {
    __shared__ __half sWt[C_OUT][WT_LD];   // W2 transposed, fp16: 13.8 KB
    __shared__ float sal[C_OUT], sar[C_OUT];
    __shared__ float sh[8][2][F1T];        // per-warp h rows for node pair: 12.8 KB
    int tid = threadIdx.x;
    for (int i = tid; i < F1T * C_OUT; i += 256) {
        int k = i >> 5, c = i & 31;        // i = k*32 + c
        sWt[c][k] = __float2half(W2[i]);
    }
    if (tid < C_OUT) { sal[tid] = al2[tid]; sar[tid] = ar2[tid]; }
    __syncthreads();

    int lane = tid & 31, wid = tid >> 5;
    bool active = lane < 25;               // lanes covering features
    bool lo0 = lane <= 12;                 // first 4 feats in head0?
    bool hi0 = lane <= 11;                 // last 4 feats in head0?

    for (int p = blockIdx.x * 8 + wid; p < N_NODES / 2; p += AG_BLOCKS * 8) {
        // ---- gather phase: node pair (2p, 2p+1) ----
        #pragma unroll
        for (int hi = 0; hi < 2; hi++) {
            int w = 2 * p + hi;
            int beg = g_off[w], end = g_off[w + 1];
            float er0 = g_er1[2 * w], er1v = g_er1[2 * w + 1];

            float acc[8] = {};
            float d0 = 0.f, d1 = 0.f;

            for (int base = beg; base < end; base += 32) {
                int n = min(32, end - base);
                int   s_l = 0;
                float w0_l = 0.f, w1_l = 0.f;
                if (lane < n) {
                    s_l = g_psrc[base + lane];
                    float2 el = *(const float2*)&g_el1[2 * s_l];
                    w0_l = __expf(lrelu(el.x + er0));
                    w1_l = __expf(lrelu(el.y + er1v));
                }
                d0 += w0_l; d1 += w1_l;

                int j = 0;
                for (; j + 2 <= n; j += 2) {
                    int   sa  = __shfl_sync(FULLM, s_l, j);
                    float w0a = __shfl_sync(FULLM, w0_l, j);
                    float w1a = __shfl_sync(FULLM, w1_l, j);
                    int   sb  = __shfl_sync(FULLM, s_l, j + 1);
                    float w0b = __shfl_sync(FULLM, w0_l, j + 1);
                    float w1b = __shfl_sync(FULLM, w1_l, j + 1);
                    if (active) {
                        const float* za = g_z1f + (size_t)sa * F1T + 8 * lane;
                        const float* zb = g_z1f + (size_t)sb * F1T + 8 * lane;
                        float4 a0 = *(const float4*)za;
                        float4 a1 = *(const float4*)(za + 4);
                        float4 b0 = *(const float4*)zb;
                        float4 b1v = *(const float4*)(zb + 4);
                        float wloa = lo0 ? w0a : w1a, whia = hi0 ? w0a : w1a;
                        float wlob = lo0 ? w0b : w1b, whib = hi0 ? w0b : w1b;
                        acc[0] += a0.x * wloa + b0.x * wlob;
                        acc[1] += a0.y * wloa + b0.y * wlob;
                        acc[2] += a0.z * wloa + b0.z * wlob;
                        acc[3] += a0.w * wloa + b0.w * wlob;
                        acc[4] += a1.x * whia + b1v.x * whib;
                        acc[5] += a1.y * whia + b1v.y * whib;
                        acc[6] += a1.z * whia + b1v.z * whib;
                        acc[7] += a1.w * whia + b1v.w * whib;
                    }
                }
                if (j < n) {
                    int   s  = __shfl_sync(FULLM, s_l, j);
                    float w0 = __shfl_sync(FULLM, w0_l, j);
                    float w1 = __shfl_sync(FULLM, w1_l, j);
                    if (active) {
                        const float* zr = g_z1f + (size_t)s * F1T + 8 * lane;
                        float4 a0 = *(const float4*)zr;
                        float4 a1 = *(const float4*)(zr + 4);
                        float wlo = lo0 ? w0 : w1, whi = hi0 ? w0 : w1;
                        acc[0] += a0.x * wlo; acc[1] += a0.y * wlo;
                        acc[2] += a0.z * wlo; acc[3] += a0.w * wlo;
                        acc[4] += a1.x * whi; acc[5] += a1.y * whi;
                        acc[6] += a1.z * whi; acc[7] += a1.w * whi;
                    }
                }
            }

            d0 = warp_sum(d0); d1 = warp_sum(d1);
            float inv0 = d0 > 0.f ? 1.f / d0 : 0.f;
            float inv1 = d1 > 0.f ? 1.f / d1 : 0.f;
            float inv_lo = lo0 ? inv0 : inv1;
            float inv_hi = hi0 ? inv0 : inv1;

            if (active) {
                float4 blo = *(const float4*)&b1[8 * lane];
                float4 bhi = *(const float4*)&b1[8 * lane + 4];
                float4 o0, o1;
                o0.x = elu1(acc[0] * inv_lo + blo.x);
                o0.y = elu1(acc[1] * inv_lo + blo.y);
                o0.z = elu1(acc[2] * inv_lo + blo.z);
                o0.w = elu1(acc[3] * inv_lo + blo.w);
                o1.x = elu1(acc[4] * inv_hi + bhi.x);
                o1.y = elu1(acc[5] * inv_hi + bhi.y);
                o1.z = elu1(acc[6] * inv_hi + bhi.z);
                o1.w = elu1(acc[7] * inv_hi + bhi.w);
                *(float4*)&sh[wid][hi][8 * lane]     = o0;
                *(float4*)&sh[wid][hi][8 * lane + 4] = o1;
            }
        }
        __syncwarp();

        // ---- paired GEMV: z2 = h . W2 for both nodes; lane = output class ----
        float accA = 0.f, accB = 0.f;
        const __half* wrow = &sWt[lane][0];
        #pragma unroll 5
        for (int k = 0; k < F1T; k += 8) {
            float4 a0 = *(const float4*)&sh[wid][0][k];
            float4 a1 = *(const float4*)&sh[wid][0][k + 4];
            float4 c0 = *(const float4*)&sh[wid][1][k];
            float4 c1 = *(const float4*)&sh[wid][1][k + 4];
            uint4 wr = *(const uint4*)&wrow[k];
            float2 wk0 = __half22float2(*reinterpret_cast<__half2*>(&wr.x));
            float2 wk1 = __half22float2(*reinterpret_cast<__half2*>(&wr.y));
            float2 wk2 = __half22float2(*reinterpret_cast<__half2*>(&wr.z));
            float2 wk3 = __half22float2(*reinterpret_cast<__half2*>(&wr.w));
            accA += a0.x * wk0.x + a0.y * wk0.y + a0.z * wk1.x + a0.w * wk1.y
                  + a1.x * wk2.x + a1.y * wk2.y + a1.z * wk3.x + a1.w * wk3.y;
            accB += c0.x * wk0.x + c0.y * wk0.y + c0.z * wk1.x + c0.w * wk1.y
                  + c1.x * wk2.x + c1.y * wk2.y + c1.z * wk3.x + c1.w * wk3.y;
        }

        int wA = 2 * p, wB = 2 * p + 1;
        g_z2h[(size_t)wA * C_OUT + lane] = __float2half(accA);
        g_z2h[(size_t)wB * C_OUT + lane] = __float2half(accB);
        float elA = warp_sum(accA * sal[lane]);
        float erA = warp_sum(accA * sar[lane]);
        float elB = warp_sum(accB * sal[lane]);
        float erB = warp_sum(accB * sar[lane]);
        if (lane == 0) {
            g_el2[wA] = elA; g_er2[wA] = erA;
            g_el2[wB] = elB; g_er2[wB] = erB;
        }
        __syncwarp();
    }
}

// ---------------- layer-2 aggregation -> output (2 edges per warp-instruction) ----------------
__global__ __launch_bounds__(256) void k_agg2(const float* __restrict__ b2,
                                              float* __restrict__ out) {
    int w = (blockIdx.x * 256 + threadIdx.x) >> 5;
    if (w >= N_NODES) return;
    int lane = threadIdx.x & 31;
    int hw = lane >> 4;            // half-warp id (edge selector)
    int li = lane & 15;            // lane within half-warp -> covers cols 2li, 2li+1
    int beg = g_off[w], end = g_off[w + 1];
    float ern = g_er2[w];

    float2 acc = make_float2(0.f, 0.f);
    float d = 0.f;
    for (int base = beg; base < end; base += 32) {
        int n = min(32, end - base);
        int   s_l = 0;
        float w_l = 0.f;
        if (lane < n) {
            s_l = g_psrc[base + lane];
            w_l = __expf(lrelu(g_el2[s_l] + ern));
        }
        d += w_l;

        int j = 0;
        for (; j + 4 <= n; j += 4) {
            int   sa = __shfl_sync(FULLM, s_l, j + hw);
            float wa = __shfl_sync(FULLM, w_l, j + hw);
            int   sb = __shfl_sync(FULLM, s_l, j + 2 + hw);
            float wb = __shfl_sync(FULLM, w_l, j + 2 + hw);
            __half2 ha = *(const __half2*)&g_z2h[(size_t)sa * C_OUT + 2 * li];
            __half2 hb = *(const __half2*)&g_z2h[(size_t)sb * C_OUT + 2 * li];
            float2 va = __half22float2(ha);
            float2 vb = __half22float2(hb);
            acc.x += va.x * wa + vb.x * wb;
            acc.y += va.y * wa + vb.y * wb;
        }
        for (; j < n; j += 2) {
            int   sa = __shfl_sync(FULLM, s_l, (j + hw) & 31);
            float wa = __shfl_sync(FULLM, w_l, (j + hw) & 31);
            __half2 ha = *(const __half2*)&g_z2h[(size_t)sa * C_OUT + 2 * li];
            float2 va = __half22float2(ha);
            acc.x += va.x * wa;
            acc.y += va.y * wa;
        }
    }

    acc.x += __shfl_xor_sync(FULLM, acc.x, 16);
    acc.y += __shfl_xor_sync(FULLM, acc.y, 16);

    d = warp_sum(d);
    float inv = d > 0.f ? 1.f / d : 0.f;

    if (hw == 0) {
        float2 bb = *(const float2*)&b2[2 * li];
        float2 o = make_float2(acc.x * inv + bb.x, acc.y * inv + bb.y);
        *(float2*)&out[(size_t)w * C_OUT + 2 * li] = o;
    }
}

// ---------------- launch ----------------
extern "C" void kernel_launch(void* const* d_in, const int* in_sizes, int n_in,
                              void* d_out, int out_size) {
    const float* features = (const float*)d_in[0];
    const float* W1  = (const float*)d_in[1];
    const float* al1 = (const float*)d_in[2];
    const float* ar1 = (const float*)d_in[3];
    const float* b1  = (const float*)d_in[4];
    const float* W2  = (const float*)d_in[5];
    const float* al2 = (const float*)d_in[6];
    const float* ar2 = (const float*)d_in[7];
    const float* b2  = (const float*)d_in[8];
    const int*   src = (const int*)d_in[9];
    const int*   dst = (const int*)d_in[10];
    float* out = (float*)d_out;

    // streams/events/symbol addrs created once, reused (host-side only)
    static cudaStream_t s2 = nullptr;
    static cudaEvent_t ev_fork = nullptr, ev_csr = nullptr;
    static void *cnt_ptr = nullptr, *el1_ptr = nullptr, *er1_ptr = nullptr;
    if (!s2) {
        cudaStreamCreateWithFlags(&s2, cudaStreamNonBlocking);
        cudaEventCreateWithFlags(&ev_fork, cudaEventDisableTiming);
        cudaEventCreateWithFlags(&ev_csr, cudaEventDisableTiming);
        cudaGetSymbolAddress(&cnt_ptr, g_cnt);
        cudaGetSymbolAddress(&el1_ptr, g_el1);
        cudaGetSymbolAddress(&er1_ptr, g_er1);
        cudaFuncSetAttribute(k_gemm1_tc, cudaFuncAttributeMaxDynamicSharedMemorySize, G1_SMEM);
    }

    cudaEventRecord(ev_fork, 0);
    cudaStreamWaitEvent(s2, ev_fork, 0);

    // CSR chain on s2: memset + histscan(1) + scatter(2)
    cudaMemsetAsync(cnt_ptr, 0, N_NODES * sizeof(int), s2);
    k_histscan<<<HS_BLOCKS, 1024, 0, s2>>>(dst);
    k_scatter<<<N_EDGES / 256, 256, 0, s2>>>(src, dst);
    cudaEventRecord(ev_csr, s2);

    // main: zero attention accumulators, then GEMM1(+attn epilogue)   [kernel 3]
    cudaMemsetAsync(el1_ptr, 0, N_NODES * NH1 * sizeof(float), 0);
    cudaMemsetAsync(er1_ptr, 0, N_NODES * NH1 * sizeof(float), 0);
    dim3 g1((N_NODES + G1_BM - 1) / G1_BM, (F1T + G1_BN - 1) / G1_BN);
    k_gemm1_tc<<<g1, 256, G1_SMEM>>>(features, W1, al1, ar1);

    // join: fused agg needs CSR + el/er + z1                           [kernel 4]
    cudaStreamWaitEvent(0, ev_csr, 0);
    k_agg1_g2<<<AG_BLOCKS, 256>>>(b1, W2, al2, ar2);

    // layer-2 aggregation                                              [kernel 5]
    k_agg2<<<N_NODES / 8, 256>>>(b2, out);
}

// round 15
// speedup vs baseline: 1.2288x; 1.2288x over previous
#include <cuda_runtime.h>
#include <cuda_fp16.h>
#include <math.h>

#define N_NODES 50000
#define N_EDGES 1600000
#define F_IN    256
#define F1T     200   // H1*F1
#define NH1     2
#define C_OUT   32
#define NEG_SLOPE 0.2f
#define FULLM   0xffffffffu

// ---------------- scratch (static device globals; no allocation) ----------------
__device__ int    g_cnt[N_NODES];
__device__ int    g_off[N_NODES + 1];
__device__ int    g_cur[N_NODES];
__device__ int    g_done;                        // last-block flag for histscan
__device__ int    g_psrc[N_EDGES];               // src node per edge, grouped by dst
__device__ __half g_z1h[(size_t)N_NODES * F1T];  // 20 MB (fp16 z1)
__device__ float  g_el1[N_NODES * NH1];
__device__ float  g_er1[N_NODES * NH1];
__device__ __half g_z2h[(size_t)N_NODES * C_OUT]; // 3.2 MB (fp16 z2)
__device__ float  g_el2[N_NODES];
__device__ float  g_er2[N_NODES];

// ---------------- helpers ----------------
__device__ __forceinline__ float warp_sum(float v) {
    #pragma unroll
    for (int o = 16; o; o >>= 1) v += __shfl_xor_sync(FULLM, v, o);
    return v;
}
__device__ __forceinline__ float lrelu(float x) { return x > 0.f ? x : NEG_SLOPE * x; }
__device__ __forceinline__ float elu1(float x)  { return x > 0.f ? x : (__expf(x) - 1.f); }
__device__ __forceinline__ unsigned tf32u(float x) {
    unsigned u;
    asm("cvt.rna.tf32.f32 %0, %1;" : "=r"(u) : "f"(x));
    return u;
}
// accumulate 8 halfs (uint4) * {wlo (first 4), whi (last 4)} into acc[8]
__device__ __forceinline__ void hfma8(float* acc, uint4 r, float wlo, float whi) {
    float2 p0 = __half22float2(*reinterpret_cast<__half2*>(&r.x));
    float2 p1 = __half22float2(*reinterpret_cast<__half2*>(&r.y));
    float2 p2 = __half22float2(*reinterpret_cast<__half2*>(&r.z));
    float2 p3 = __half22float2(*reinterpret_cast<__half2*>(&r.w));
    acc[0] += p0.x * wlo; acc[1] += p0.y * wlo;
    acc[2] += p1.x * wlo; acc[3] += p1.y * wlo;
    acc[4] += p2.x * whi; acc[5] += p2.y * whi;
    acc[6] += p3.x * whi; acc[7] += p3.y * whi;
}

__device__ __forceinline__ unsigned smem_u32(const void* p) {
    return (unsigned)__cvta_generic_to_shared(p);
}
__device__ __forceinline__ void cp_async16(void* dst_smem, const void* src_gmem) {
    asm volatile("cp.async.cg.shared.global [%0], [%1], 16;\n"
                 :: "r"(smem_u32(dst_smem)), "l"(src_gmem));
}
__device__ __forceinline__ void cp_commit() { asm volatile("cp.async.commit_group;\n"); }
template <int N>
__device__ __forceinline__ void cp_wait() { asm volatile("cp.async.wait_group %0;\n" :: "n"(N)); }

// ---------------- CSR build: fused hist + scan (last-block pattern) ----------------
#define HS_BLOCKS ((N_EDGES + 1023) / 1024)   // 1563
__global__ __launch_bounds__(1024) void k_histscan(const int* __restrict__ dst) {
    int tid = threadIdx.x;
    int e = blockIdx.x * 1024 + tid;
    if (e < N_EDGES) atomicAdd(&g_cnt[dst[e]], 1);

    __threadfence();
    __shared__ int s_last;
    __syncthreads();
    if (tid == 0) s_last = (atomicAdd(&g_done, 1) == gridDim.x - 1);
    __syncthreads();
    if (!s_last) return;

    const int CH = (N_NODES + 1023) / 1024;  // 49
    int beg = tid * CH;
    int end = min(beg + CH, N_NODES);
    int s = 0;
    for (int i = beg; i < end; i++) s += g_cnt[i];

    __shared__ int warp_sums[32];
    int lane = tid & 31, wid = tid >> 5;
    int v = s;
    #pragma unroll
    for (int o = 1; o < 32; o <<= 1) {
        int t = __shfl_up_sync(FULLM, v, o);
        if (lane >= o) v += t;
    }
    if (lane == 31) warp_sums[wid] = v;
    __syncthreads();
    if (wid == 0) {
        int w = warp_sums[lane];
        #pragma unroll
        for (int o = 1; o < 32; o <<= 1) {
            int t = __shfl_up_sync(FULLM, w, o);
            if (lane >= o) w += t;
        }
        warp_sums[lane] = w;
    }
    __syncthreads();
    int excl = (v - s) + (wid > 0 ? warp_sums[wid - 1] : 0);
    int run = excl;
    for (int i = beg; i < end; i++) {
        int c = g_cnt[i];
        g_off[i] = run;
        g_cur[i] = run;
        run += c;
    }
    if (tid == 1023) g_off[N_NODES] = run;
    if (tid == 0) g_done = 0;   // reset for next replay
}

__global__ void k_scatter(const int* __restrict__ src, const int* __restrict__ dst) {
    int e = blockIdx.x * blockDim.x + threadIdx.x;
    if (e < N_EDGES) {
        int p = atomicAdd(&g_cur[dst[e]], 1);
        g_psrc[p] = src[e];
    }
}

// ---------------- GEMM1 (tf32 mma) -> z1 fp16, + fused attention coefs ----------------
#define G1_BM 128
#define G1_BN 64
#define G1_BK 32
#define G1_LDA 36
#define G1_LDB 72
#define A_STAGE (G1_BM * G1_LDA)
#define B_STAGE (G1_BK * G1_LDB)
#define G1_SMEM ((2 * A_STAGE + 2 * B_STAGE) * 4)   // 55296 bytes dynamic
#define G1_NIT  (F_IN / G1_BK)

__device__ __forceinline__ void mma_tf32(float* d, const unsigned* a, const unsigned* b) {
    asm volatile(
        "mma.sync.aligned.m16n8k8.row.col.f32.tf32.tf32.f32 "
        "{%0,%1,%2,%3}, {%4,%5,%6,%7}, {%8,%9}, {%0,%1,%2,%3};"
        : "+f"(d[0]), "+f"(d[1]), "+f"(d[2]), "+f"(d[3])
        : "r"(a[0]), "r"(a[1]), "r"(a[2]), "r"(a[3]), "r"(b[0]), "r"(b[1]));
}

__global__ __launch_bounds__(256) void k_gemm1_tc(const float* __restrict__ A,
                                                  const float* __restrict__ B,
                                                  const float* __restrict__ al1,
                                                  const float* __restrict__ ar1) {
    extern __shared__ float smem[];
    float* sA = smem;                      // [2][128][36]
    float* sB = smem + 2 * A_STAGE;        // [2][32][72]
    __shared__ float s_al[F1T], s_ar[F1T];

    int tid = threadIdx.x;
    int lane = tid & 31, wid = tid >> 5;
    int wm = wid & 3, wn = wid >> 2;
    int bm = blockIdx.x * G1_BM, bn = blockIdx.y * G1_BN;
    int q = lane >> 2, r = lane & 3;

    for (int i = tid; i < F1T; i += 256) { s_al[i] = al1[i]; s_ar[i] = ar1[i]; }

    int am = tid >> 3;
    int akc = (tid & 7) * 4;

    auto load_stage = [&](int st, int k0) {
        float* a_s = sA + st * A_STAGE;
        float* b_s = sB + st * B_STAGE;
        #pragma unroll
        for (int it = 0; it < 4; it++) {
            int m = am + it * 32;
            float* dstp = &a_s[m * G1_LDA + akc];
            if (bm + m < N_NODES)
                cp_async16(dstp, &A[(size_t)(bm + m) * F_IN + k0 + akc]);
            else
                *(float4*)dstp = make_float4(0.f, 0.f, 0.f, 0.f);
        }
        #pragma unroll
        for (int it = 0; it < 2; it++) {
            int idx = tid + it * 256;
            int kk = idx >> 4;
            int nc = (idx & 15) * 4;
            float* dstp = &b_s[kk * G1_LDB + nc];
            if (bn + nc < F1T)
                cp_async16(dstp, &B[(size_t)(k0 + kk) * F1T + bn + nc]);
            else
                *(float4*)dstp = make_float4(0.f, 0.f, 0.f, 0.f);
        }
        cp_commit();
    };

    float acc[2][4][4] = {};

    load_stage(0, 0);

    #pragma unroll
    for (int it = 0; it < G1_NIT; it++) {
        if (it + 1 < G1_NIT) {
            load_stage((it + 1) & 1, (it + 1) * G1_BK);
            cp_wait<1>();
        } else {
            cp_wait<0>();
        }
        __syncthreads();

        const float* a_s = sA + (it & 1) * A_STAGE;
        const float* b_s = sB + (it & 1) * B_STAGE;

        #pragma unroll
        for (int k8 = 0; k8 < G1_BK / 8; k8++) {
            int kb = k8 * 8;
            unsigned af[2][4], bf[4][2];
            #pragma unroll
            for (int mt = 0; mt < 2; mt++) {
                int m0 = wm * 32 + mt * 16 + q;
                af[mt][0] = tf32u(a_s[m0 * G1_LDA + kb + r]);
                af[mt][1] = tf32u(a_s[(m0 + 8) * G1_LDA + kb + r]);
                af[mt][2] = tf32u(a_s[m0 * G1_LDA + kb + r + 4]);
                af[mt][3] = tf32u(a_s[(m0 + 8) * G1_LDA + kb + r + 4]);
            }
            #pragma unroll
            for (int nt = 0; nt < 4; nt++) {
                int n0 = wn * 32 + nt * 8 + q;
                bf[nt][0] = tf32u(b_s[(kb + r) * G1_LDB + n0]);
                bf[nt][1] = tf32u(b_s[(kb + r + 4) * G1_LDB + n0]);
            }
            #pragma unroll
            for (int mt = 0; mt < 2; mt++)
                #pragma unroll
                for (int nt = 0; nt < 4; nt++)
                    mma_tf32(acc[mt][nt], af[mt], bf[nt]);
        }
        __syncthreads();
    }

    // epilogue A: store z1 as half2
    #pragma unroll
    for (int mt = 0; mt < 2; mt++) {
        #pragma unroll
        for (int nt = 0; nt < 4; nt++) {
            int row = bm + wm * 32 + mt * 16 + q;
            int col = bn + wn * 32 + nt * 8 + 2 * r;
            if (col < F1T) {
                if (row < N_NODES) {
                    __half2 hv = __floats2half2_rn(acc[mt][nt][0], acc[mt][nt][1]);
                    *(__half2*)&g_z1h[(size_t)row * F1T + col] = hv;
                }
                if (row + 8 < N_NODES) {
                    __half2 hv = __floats2half2_rn(acc[mt][nt][2], acc[mt][nt][3]);
                    *(__half2*)&g_z1h[(size_t)(row + 8) * F1T + col] = hv;
                }
            }
        }
    }

    // epilogue B: partial el/er per row
    #pragma unroll
    for (int mt = 0; mt < 2; mt++) {
        float e0l = 0.f, e1l = 0.f, e0r = 0.f, e1r = 0.f;   // row r0
        float f0l = 0.f, f1l = 0.f, f0r = 0.f, f1r = 0.f;   // row r0+8
        #pragma unroll
        for (int nt = 0; nt < 4; nt++) {
            int colb = bn + wn * 32 + nt * 8 + 2 * r;
            #pragma unroll
            for (int cc = 0; cc < 2; cc++) {
                int c = colb + cc;
                if (c < F1T) {
                    float a = s_al[c], rr = s_ar[c];
                    float zt = acc[mt][nt][cc];
                    float zb = acc[mt][nt][2 + cc];
                    if (c < 100) { e0l += zt * a; e0r += zt * rr; f0l += zb * a; f0r += zb * rr; }
                    else         { e1l += zt * a; e1r += zt * rr; f1l += zb * a; f1r += zb * rr; }
                }
            }
        }
        #pragma unroll
        for (int o = 1; o <= 2; o <<= 1) {
            e0l += __shfl_xor_sync(FULLM, e0l, o); e1l += __shfl_xor_sync(FULLM, e1l, o);
            e0r += __shfl_xor_sync(FULLM, e0r, o); e1r += __shfl_xor_sync(FULLM, e1r, o);
            f0l += __shfl_xor_sync(FULLM, f0l, o); f1l += __shfl_xor_sync(FULLM, f1l, o);
            f0r += __shfl_xor_sync(FULLM, f0r, o); f1r += __shfl_xor_sync(FULLM, f1r, o);
        }
        if (r == 0) {
            int row = bm + wm * 32 + mt * 16 + q;
            if (row < N_NODES) {
                atomicAdd(&g_el1[2 * row],     e0l); atomicAdd(&g_el1[2 * row + 1], e1l);
                atomicAdd(&g_er1[2 * row],     e0r); atomicAdd(&g_er1[2 * row + 1], e1r);
            }
            if (row + 8 < N_NODES) {
                atomicAdd(&g_el1[2 * (row + 8)],     f0l); atomicAdd(&g_el1[2 * (row + 8) + 1], f1l);
                atomicAdd(&g_er1[2 * (row + 8)],     f0r); atomicAdd(&g_er1[2 * (row + 8) + 1], f1r);
            }
        }
    }
}

// ---------------- fused layer-1 aggregation + ELU + GEMM2 (paired) + attn2 coefs ----------------
// Gather layout: lane l (<25) covers features 8l..8l+7 via ONE 16B load per edge.
// Byte offsets (s*400, fits 32-bit) are broadcast instead of node indices to
// remove the per-edge 64-bit multiply in the consume loop.
#define AG_BLOCKS (6 * 148)   // 888: one wave at 6 blocks/SM
#define WT_LD 216             // padded row (halfs): conflict-free int4 reads
__global__ __launch_bounds__(256, 6) void k_agg1_g2(const float* __restrict__ b1,
                                                    const float* __restrict__ W2,
                                                    const float* __restrict__ al2,
                                                    const float* __restrict__ ar2) {
    __shared__ __half sWt[C_OUT][WT_LD];   // W2 transposed, fp16: 13.8 KB
    __shared__ float sal[C_OUT], sar[C_OUT];
    __shared__ float sh[8][2][F1T];        // per-warp h rows for node pair: 12.8 KB
    int tid = threadIdx.x;
    for (int i = tid; i < F1T * C_OUT; i += 256) {
        int k = i >> 5, c = i & 31;        // i = k*32 + c
        sWt[c][k] = __float2half(W2[i]);
    }
    if (tid < C_OUT) { sal[tid] = al2[tid]; sar[tid] = ar2[tid]; }
    __syncthreads();

    int lane = tid & 31, wid = tid >> 5;
    bool active = lane < 25;               // lanes covering features
    bool lo0 = lane <= 12;                 // first 4 feats in head0?
    bool hi0 = lane <= 11;                 // last 4 feats in head0?
    const char* zbase = (const char*)g_z1h + 16 * lane;   // per-lane base

    for (int p = blockIdx.x * 8 + wid; p < N_NODES / 2; p += AG_BLOCKS * 8) {
        // ---- gather phase: node pair (2p, 2p+1) ----
        #pragma unroll
        for (int hi = 0; hi < 2; hi++) {
            int w = 2 * p + hi;
            int beg = g_off[w], end = g_off[w + 1];
            float er0 = g_er1[2 * w], er1v = g_er1[2 * w + 1];

            float acc[8] = {};
            float d0 = 0.f, d1 = 0.f;

            for (int base = beg; base < end; base += 32) {
                int n = min(32, end - base);
                unsigned off_l = 0;
                float w0_l = 0.f, w1_l = 0.f;
                if (lane < n) {
                    int s_l = g_psrc[base + lane];
                    float2 el = *(const float2*)&g_el1[2 * s_l];
                    w0_l = __expf(lrelu(el.x + er0));
                    w1_l = __expf(lrelu(el.y + er1v));
                    off_l = (unsigned)s_l * (F1T * 2);   // byte offset, once per chunk
                }
                d0 += w0_l; d1 += w1_l;

                int j = 0;
                for (; j + 2 <= n; j += 2) {
                    unsigned oa = __shfl_sync(FULLM, off_l, j);
                    float w0a = __shfl_sync(FULLM, w0_l, j);
                    float w1a = __shfl_sync(FULLM, w1_l, j);
                    unsigned ob = __shfl_sync(FULLM, off_l, j + 1);
                    float w0b = __shfl_sync(FULLM, w0_l, j + 1);
                    float w1b = __shfl_sync(FULLM, w1_l, j + 1);
                    if (active) {
                        uint4 ra = *(const uint4*)(zbase + oa);
                        uint4 rb = *(const uint4*)(zbase + ob);
                        hfma8(acc, ra, lo0 ? w0a : w1a, hi0 ? w0a : w1a);
                        hfma8(acc, rb, lo0 ? w0b : w1b, hi0 ? w0b : w1b);
                    }
                }
                if (j < n) {
                    unsigned oo = __shfl_sync(FULLM, off_l, j);
                    float w0 = __shfl_sync(FULLM, w0_l, j);
                    float w1 = __shfl_sync(FULLM, w1_l, j);
                    if (active) {
                        uint4 rr = *(const uint4*)(zbase + oo);
                        hfma8(acc, rr, lo0 ? w0 : w1, hi0 ? w0 : w1);
                    }
                }
            }

            d0 = warp_sum(d0); d1 = warp_sum(d1);
            float inv0 = d0 > 0.f ? 1.f / d0 : 0.f;
            float inv1 = d1 > 0.f ? 1.f / d1 : 0.f;
            float inv_lo = lo0 ? inv0 : inv1;
            float inv_hi = hi0 ? inv0 : inv1;

            if (active) {
                float4 blo = *(const float4*)&b1[8 * lane];
                float4 bhi = *(const float4*)&b1[8 * lane + 4];
                float4 o0, o1;
                o0.x = elu1(acc[0] * inv_lo + blo.x);
                o0.y = elu1(acc[1] * inv_lo + blo.y);
                o0.z = elu1(acc[2] * inv_lo + blo.z);
                o0.w = elu1(acc[3] * inv_lo + blo.w);
                o1.x = elu1(acc[4] * inv_hi + bhi.x);
                o1.y = elu1(acc[5] * inv_hi + bhi.y);
                o1.z = elu1(acc[6] * inv_hi + bhi.z);
                o1.w = elu1(acc[7] * inv_hi + bhi.w);
                *(float4*)&sh[wid][hi][8 * lane]     = o0;
                *(float4*)&sh[wid][hi][8 * lane + 4] = o1;
            }
        }
        __syncwarp();

        // ---- paired GEMV: z2 = h . W2 for both nodes; lane = output class ----
        float accA = 0.f, accB = 0.f;
        const __half* wrow = &sWt[lane][0];
        #pragma unroll 5
        for (int k = 0; k < F1T; k += 8) {
            float4 a0 = *(const float4*)&sh[wid][0][k];
            float4 a1 = *(const float4*)&sh[wid][0][k + 4];
            float4 c0 = *(const float4*)&sh[wid][1][k];
            float4 c1 = *(const float4*)&sh[wid][1][k + 4];
            uint4 wr = *(const uint4*)&wrow[k];
            float2 wk0 = __half22float2(*reinterpret_cast<__half2*>(&wr.x));
            float2 wk1 = __half22float2(*reinterpret_cast<__half2*>(&wr.y));
            float2 wk2 = __half22float2(*reinterpret_cast<__half2*>(&wr.z));
            float2 wk3 = __half22float2(*reinterpret_cast<__half2*>(&wr.w));
            accA += a0.x * wk0.x + a0.y * wk0.y + a0.z * wk1.x + a0.w * wk1.y
                  + a1.x * wk2.x + a1.y * wk2.y + a1.z * wk3.x + a1.w * wk3.y;
            accB += c0.x * wk0.x + c0.y * wk0.y + c0.z * wk1.x + c0.w * wk1.y
                  + c1.x * wk2.x + c1.y * wk2.y + c1.z * wk3.x + c1.w * wk3.y;
        }

        int wA = 2 * p, wB = 2 * p + 1;
        g_z2h[(size_t)wA * C_OUT + lane] = __float2half(accA);
        g_z2h[(size_t)wB * C_OUT + lane] = __float2half(accB);
        float elA = warp_sum(accA * sal[lane]);
        float erA = warp_sum(accA * sar[lane]);
        float elB = warp_sum(accB * sal[lane]);
        float erB = warp_sum(accB * sar[lane]);
        if (lane == 0) {
            g_el2[wA] = elA; g_er2[wA] = erA;
            g_el2[wB] = elB; g_er2[wB] = erB;
        }
        __syncwarp();
    }
}

// ---------------- layer-2 aggregation -> output (2 edges per warp-instruction) ----------------
__global__ __launch_bounds__(256) void k_agg2(const float* __restrict__ b2,
                                              float* __restrict__ out) {
    int w = (blockIdx.x * 256 + threadIdx.x) >> 5;
    if (w >= N_NODES) return;
    int lane = threadIdx.x & 31;
    int hw = lane >> 4;            // half-warp id (edge selector)
    int li = lane & 15;            // lane within half-warp -> covers cols 2li, 2li+1
    int beg = g_off[w], end = g_off[w + 1];
    float ern = g_er2[w];

    float2 acc = make_float2(0.f, 0.f);
    float d = 0.f;
    for (int base = beg; base < end; base += 32) {
        int n = min(32, end - base);
        int   s_l = 0;
        float w_l = 0.f;
        if (lane < n) {
            s_l = g_psrc[base + lane];
            w_l = __expf(lrelu(g_el2[s_l] + ern));
        }
        d += w_l;

        int j = 0;
        for (; j + 4 <= n; j += 4) {
            int   sa = __shfl_sync(FULLM, s_l, j + hw);
            float wa = __shfl_sync(FULLM, w_l, j + hw);
            int   sb = __shfl_sync(FULLM, s_l, j + 2 + hw);
            float wb = __shfl_sync(FULLM, w_l, j + 2 + hw);
            __half2 ha = *(const __half2*)&g_z2h[(size_t)sa * C_OUT + 2 * li];
            __half2 hb = *(const __half2*)&g_z2h[(size_t)sb * C_OUT + 2 * li];
            float2 va = __half22float2(ha);
            float2 vb = __half22float2(hb);
            acc.x += va.x * wa + vb.x * wb;
            acc.y += va.y * wa + vb.y * wb;
        }
        for (; j < n; j += 2) {
            int   sa = __shfl_sync(FULLM, s_l, (j + hw) & 31);
            float wa = __shfl_sync(FULLM, w_l, (j + hw) & 31);
            __half2 ha = *(const __half2*)&g_z2h[(size_t)sa * C_OUT + 2 * li];
            float2 va = __half22float2(ha);
            acc.x += va.x * wa;
            acc.y += va.y * wa;
        }
    }

    acc.x += __shfl_xor_sync(FULLM, acc.x, 16);
    acc.y += __shfl_xor_sync(FULLM, acc.y, 16);

    d = warp_sum(d);
    float inv = d > 0.f ? 1.f / d : 0.f;

    if (hw == 0) {
        float2 bb = *(const float2*)&b2[2 * li];
        float2 o = make_float2(acc.x * inv + bb.x, acc.y * inv + bb.y);
        *(float2*)&out[(size_t)w * C_OUT + 2 * li] = o;
    }
}

// ---------------- launch ----------------
extern "C" void kernel_launch(void* const* d_in, const int* in_sizes, int n_in,
                              void* d_out, int out_size) {
    const float* features = (const float*)d_in[0];
    const float* W1  = (const float*)d_in[1];
    const float* al1 = (const float*)d_in[2];
    const float* ar1 = (const float*)d_in[3];
    const float* b1  = (const float*)d_in[4];
    const float* W2  = (const float*)d_in[5];
    const float* al2 = (const float*)d_in[6];
    const float* ar2 = (const float*)d_in[7];
    const float* b2  = (const float*)d_in[8];
    const int*   src = (const int*)d_in[9];
    const int*   dst = (const int*)d_in[10];
    float* out = (float*)d_out;

    // streams/events/symbol addrs created once, reused (host-side only)
    static cudaStream_t s2 = nullptr;
    static cudaEvent_t ev_fork = nullptr, ev_csr = nullptr;
    static void *cnt_ptr = nullptr, *el1_ptr = nullptr, *er1_ptr = nullptr;
    if (!s2) {
        cudaStreamCreateWithFlags(&s2, cudaStreamNonBlocking);
        cudaEventCreateWithFlags(&ev_fork, cudaEventDisableTiming);
        cudaEventCreateWithFlags(&ev_csr, cudaEventDisableTiming);
        cudaGetSymbolAddress(&cnt_ptr, g_cnt);
        cudaGetSymbolAddress(&el1_ptr, g_el1);
        cudaGetSymbolAddress(&er1_ptr, g_er1);
        cudaFuncSetAttribute(k_gemm1_tc, cudaFuncAttributeMaxDynamicSharedMemorySize, G1_SMEM);
    }

    cudaEventRecord(ev_fork, 0);
    cudaStreamWaitEvent(s2, ev_fork, 0);

    // CSR chain on s2: memset + histscan(1) + scatter(2)
    cudaMemsetAsync(cnt_ptr, 0, N_NODES * sizeof(int), s2);
    k_histscan<<<HS_BLOCKS, 1024, 0, s2>>>(dst);
    k_scatter<<<N_EDGES / 256, 256, 0, s2>>>(src, dst);
    cudaEventRecord(ev_csr, s2);

    // main: zero attention accumulators, then GEMM1(+attn epilogue)   [kernel 3]
    cudaMemsetAsync(el1_ptr, 0, N_NODES * NH1 * sizeof(float), 0);
    cudaMemsetAsync(er1_ptr, 0, N_NODES * NH1 * sizeof(float), 0);
    dim3 g1((N_NODES + G1_BM - 1) / G1_BM, (F1T + G1_BN - 1) / G1_BN);
    k_gemm1_tc<<<g1, 256, G1_SMEM>>>(features, W1, al1, ar1);

    // join: fused agg needs CSR + el/er + z1                           [kernel 4]
    cudaStreamWaitEvent(0, ev_csr, 0);
    k_agg1_g2<<<AG_BLOCKS, 256>>>(b1, W2, al2, ar2);

    // layer-2 aggregation                                              [kernel 5]
    k_agg2<<<N_NODES / 8, 256>>>(b2, out);
}